// round 4
// baseline (speedup 1.0000x reference)
#include <cuda_runtime.h>
#include <cstdint>

// LIF recurrence over 4 timesteps.
// x: [T=4, N=8388608] fp32, out: same shape.
// Forward math (stop_gradient makes surrogate vanish in fwd):
//   mem = 0.25*mem + x[t]; spike = mem > 0.5 ? 1 : 0; out[t]=spike; mem *= (1-spike)
//
// HBM-bound: 256 MiB total traffic. float4 vectorized, streaming loads/stores.

static constexpr float DECAY = 0.25f;
static constexpr float THRESH = 0.5f;   // V_TH = 1.0, so mem/V_TH > 0.5 <=> mem > 0.5

__global__ __launch_bounds__(256)
void lif_kernel(const float4* __restrict__ x, float4* __restrict__ out, int n4) {
    int i = blockIdx.x * blockDim.x + threadIdx.x;
    if (i >= n4) return;

    float4 mem = make_float4(0.f, 0.f, 0.f, 0.f);

    #pragma unroll
    for (int t = 0; t < 4; ++t) {
        const size_t idx = (size_t)t * (size_t)n4 + (size_t)i;
        float4 xt = __ldcs(x + idx);   // streaming: no reuse, don't pollute L2

        float4 sp;

        mem.x = fmaf(mem.x, DECAY, xt.x);
        sp.x  = (mem.x > THRESH) ? 1.f : 0.f;
        mem.x = (mem.x > THRESH) ? 0.f : mem.x;

        mem.y = fmaf(mem.y, DECAY, xt.y);
        sp.y  = (mem.y > THRESH) ? 1.f : 0.f;
        mem.y = (mem.y > THRESH) ? 0.f : mem.y;

        mem.z = fmaf(mem.z, DECAY, xt.z);
        sp.z  = (mem.z > THRESH) ? 1.f : 0.f;
        mem.z = (mem.z > THRESH) ? 0.f : mem.z;

        mem.w = fmaf(mem.w, DECAY, xt.w);
        sp.w  = (mem.w > THRESH) ? 1.f : 0.f;
        mem.w = (mem.w > THRESH) ? 0.f : mem.w;

        __stcs(out + idx, sp);          // streaming store
    }
}

extern "C" void kernel_launch(void* const* d_in, const int* in_sizes, int n_in,
                              void* d_out, int out_size) {
    const float* x = (const float*)d_in[0];
    float* out = (float*)d_out;

    // Total elements = T * N; T = 4 (leading dim of the scan).
    const int total = in_sizes[0];          // 33,554,432
    const int n = total / 4;                // spatial elements per timestep
    const int n4 = n / 4;                   // float4 groups per timestep (N % 4 == 0)

    const int threads = 256;
    const int blocks = (n4 + threads - 1) / threads;

    lif_kernel<<<blocks, threads>>>((const float4*)x, (float4*)out, n4);
}

// round 5
// speedup vs baseline: 1.0028x; 1.0028x over previous
#include <cuda_runtime.h>
#include <cstdint>

// LIF recurrence over 4 timesteps, forward-value only:
//   mem = 0.25*mem + x[t]; spike = mem > 0.5; out[t] = spike; mem = spike ? 0 : mem
//
// x/out: [T=4, N=8388608] fp32. Pure streaming, HBM-bound (256 MiB traffic).
// R4 change: load ALL inputs first (8 LDG.128 in flight per thread: 2 spatial
// groups x 4 timesteps), compute in regs, then batch ALL stores. Maximizes MLP
// so DRAM utilization rises from 69% toward the ~85% streaming ceiling.

static constexpr float DECAY  = 0.25f;
static constexpr float THRESH = 0.5f;   // V_TH=1: mem/V_TH > 0.5 <=> mem > 0.5

__device__ __forceinline__ void lif_step(float& mem, const float x, float& sp) {
    mem = fmaf(mem, DECAY, x);
    bool s = mem > THRESH;
    sp  = s ? 1.f : 0.f;
    mem = s ? 0.f : mem;
}

__device__ __forceinline__ void lif_step4(float4& mem, float4& io /* in: x, out: spike */) {
    lif_step(mem.x, io.x, io.x);
    lif_step(mem.y, io.y, io.y);
    lif_step(mem.z, io.z, io.z);
    lif_step(mem.w, io.w, io.w);
}

__global__ __launch_bounds__(256)
void lif_kernel(const float4* __restrict__ x, float4* __restrict__ out, int n4) {
    // Two adjacent-coalesced float4 groups per thread.
    const int i0 = blockIdx.x * (blockDim.x * 2) + threadIdx.x;
    const int i1 = i0 + blockDim.x;
    if (i1 >= n4) {
        // tail path (not taken for the bench shape; kept for safety)
        if (i0 < n4) {
            float4 mem = make_float4(0.f, 0.f, 0.f, 0.f);
            #pragma unroll
            for (int t = 0; t < 4; ++t) {
                size_t idx = (size_t)t * n4 + i0;
                float4 v = __ldcs(x + idx);
                lif_step4(mem, v);
                __stcs(out + idx, v);
            }
        }
        return;
    }

    // ---- read phase: 8 independent LDG.128 in flight ----
    float4 a0 = __ldcs(x + (size_t)0 * n4 + i0);
    float4 b0 = __ldcs(x + (size_t)0 * n4 + i1);
    float4 a1 = __ldcs(x + (size_t)1 * n4 + i0);
    float4 b1 = __ldcs(x + (size_t)1 * n4 + i1);
    float4 a2 = __ldcs(x + (size_t)2 * n4 + i0);
    float4 b2 = __ldcs(x + (size_t)2 * n4 + i1);
    float4 a3 = __ldcs(x + (size_t)3 * n4 + i0);
    float4 b3 = __ldcs(x + (size_t)3 * n4 + i1);

    // ---- compute phase: two independent recurrence chains (ILP=2) ----
    float4 memA = make_float4(0.f, 0.f, 0.f, 0.f);
    float4 memB = make_float4(0.f, 0.f, 0.f, 0.f);
    lif_step4(memA, a0);  lif_step4(memB, b0);
    lif_step4(memA, a1);  lif_step4(memB, b1);
    lif_step4(memA, a2);  lif_step4(memB, b2);
    lif_step4(memA, a3);  lif_step4(memB, b3);

    // ---- write phase: batched streaming stores ----
    __stcs(out + (size_t)0 * n4 + i0, a0);
    __stcs(out + (size_t)0 * n4 + i1, b0);
    __stcs(out + (size_t)1 * n4 + i0, a1);
    __stcs(out + (size_t)1 * n4 + i1, b1);
    __stcs(out + (size_t)2 * n4 + i0, a2);
    __stcs(out + (size_t)2 * n4 + i1, b2);
    __stcs(out + (size_t)3 * n4 + i0, a3);
    __stcs(out + (size_t)3 * n4 + i1, b3);
}

extern "C" void kernel_launch(void* const* d_in, const int* in_sizes, int n_in,
                              void* d_out, int out_size) {
    const float* x = (const float*)d_in[0];
    float* out = (float*)d_out;

    const int total = in_sizes[0];          // T*N = 33,554,432
    const int n = total / 4;                // N per timestep
    const int n4 = n / 4;                   // float4 groups per timestep

    const int threads = 256;
    const int groups_per_block = threads * 2;
    const int blocks = (n4 + groups_per_block - 1) / groups_per_block;  // 4096

    lif_kernel<<<blocks, threads>>>((const float4*)x, (float4*)out, n4);
}